// round 1
// baseline (speedup 1.0000x reference)
#include <cuda_runtime.h>
#include <cuda_bf16.h>
#include <math.h>

// Problem constants
#define BB 16
#define TT 2000
#define MM (BB*TT)        // 32000
#define DENC 512
#define VV 1024
#define EE 256
#define PP 640
#define JJ 640

// ---------------- scratch (device globals; no allocation allowed) -----------
__device__ float g_enc[(size_t)MM * VV];     // encoder logits
__device__ float g_pred[(size_t)MM * VV];    // predictor logits
__device__ float g_logits[(size_t)MM * VV];  // joint logits
__device__ float g_buf1[(size_t)MM * PP];    // a1 / h
__device__ float g_buf2[(size_t)MM * PP];    // a2
__device__ int2  g_ctx[MM];                  // (c[t], c[t-1])

// ---------------- context scan ----------------------------------------------
__global__ void ctx_kernel(const int* __restrict__ targets) {
    int b = threadIdx.x;
    if (b >= BB) return;
    int run = 0;     // last non-blank target strictly before t
    int prev = 0;    // c[t-1]
    const int* tg = targets + (size_t)b * TT;
    int2* out = g_ctx + (size_t)b * TT;
    for (int t = 0; t < TT; ++t) {
        int c = run;
        out[t] = make_int2(c, prev);
        int v = tg[t];
        if (v != 0) run = v;
        prev = c;
    }
}

// ---------------- SGEMM: C = act(A @ B + bias) -------------------------------
// ASRC: 0 = A plain [M,K] row-major
//       1 = A gathered from emb via g_ctx: A[m,k] = emb[(k<256?c0:c1), k&255]
//       2 = A = A1 + A2 (elementwise)
// ACT:  0 = identity, 1 = tanh
template<int ASRC, int ACT>
__global__ __launch_bounds__(256) void sgemm_kernel(
    const float* __restrict__ A, const float* __restrict__ A2,
    const int2* __restrict__ ctx, const float* __restrict__ emb,
    const float* __restrict__ Bm, const float* __restrict__ bias,
    float* __restrict__ C, int M, int N, int K)
{
    const int BM = 128, BN = 128, BK = 8;
    __shared__ __align__(16) float As[BK][BM];
    __shared__ __align__(16) float Bs[BK][BN];

    int tid = threadIdx.x;            // 0..255
    int tx = tid & 15;                // col group (8 cols each)
    int ty = tid >> 4;                // row group (8 rows each)

    int gRow = blockIdx.y * BM;
    int gCol = blockIdx.x * BN;

    // A tile load mapping: 128 rows x 8 cols, float4 per thread
    int rowA = tid >> 1;
    int colA = (tid & 1) * 4;
    // B tile load mapping: 8 rows x 128 cols, float4 per thread
    int rowB = tid >> 5;
    int colB = (tid & 31) * 4;

    float acc[8][8];
    #pragma unroll
    for (int i = 0; i < 8; ++i)
        #pragma unroll
        for (int j = 0; j < 8; ++j) acc[i][j] = 0.f;

    for (int k0 = 0; k0 < K; k0 += BK) {
        // ---- load A tile
        float4 av;
        int m = gRow + rowA;
        int k = k0 + colA;
        if (ASRC == 0) {
            av = *reinterpret_cast<const float4*>(A + (size_t)m * K + k);
        } else if (ASRC == 1) {
            int2 cx = ctx[m];
            int idx = (k < 256) ? cx.x : cx.y;
            av = *reinterpret_cast<const float4*>(emb + (size_t)idx * EE + (k & 255));
        } else {
            float4 v1 = *reinterpret_cast<const float4*>(A  + (size_t)m * K + k);
            float4 v2 = *reinterpret_cast<const float4*>(A2 + (size_t)m * K + k);
            av = make_float4(v1.x + v2.x, v1.y + v2.y, v1.z + v2.z, v1.w + v2.w);
        }
        As[colA + 0][rowA] = av.x;
        As[colA + 1][rowA] = av.y;
        As[colA + 2][rowA] = av.z;
        As[colA + 3][rowA] = av.w;

        // ---- load B tile
        float4 bv = *reinterpret_cast<const float4*>(Bm + (size_t)(k0 + rowB) * N + gCol + colB);
        *reinterpret_cast<float4*>(&Bs[rowB][colB]) = bv;

        __syncthreads();

        #pragma unroll
        for (int kk = 0; kk < BK; ++kk) {
            float ar[8], br[8];
            *reinterpret_cast<float4*>(ar)     = *reinterpret_cast<const float4*>(&As[kk][ty * 8]);
            *reinterpret_cast<float4*>(ar + 4) = *reinterpret_cast<const float4*>(&As[kk][ty * 8 + 4]);
            *reinterpret_cast<float4*>(br)     = *reinterpret_cast<const float4*>(&Bs[kk][tx * 8]);
            *reinterpret_cast<float4*>(br + 4) = *reinterpret_cast<const float4*>(&Bs[kk][tx * 8 + 4]);
            #pragma unroll
            for (int i = 0; i < 8; ++i)
                #pragma unroll
                for (int j = 0; j < 8; ++j)
                    acc[i][j] = fmaf(ar[i], br[j], acc[i][j]);
        }
        __syncthreads();
    }

    // ---- epilogue: bias + activation + store
    float bvals[8];
    #pragma unroll
    for (int j = 0; j < 8; ++j) bvals[j] = bias[gCol + tx * 8 + j];

    #pragma unroll
    for (int i = 0; i < 8; ++i) {
        size_t roff = (size_t)(gRow + ty * 8 + i) * N + gCol + tx * 8;
        #pragma unroll
        for (int j = 0; j < 8; j += 4) {
            float4 o;
            o.x = acc[i][j + 0] + bvals[j + 0];
            o.y = acc[i][j + 1] + bvals[j + 1];
            o.z = acc[i][j + 2] + bvals[j + 2];
            o.w = acc[i][j + 3] + bvals[j + 3];
            if (ACT == 1) {
                o.x = tanhf(o.x); o.y = tanhf(o.y);
                o.z = tanhf(o.z); o.w = tanhf(o.w);
            }
            *reinterpret_cast<float4*>(&C[roff + j]) = o;
        }
    }
}

// ---------------- row-wise log-softmax over V=1024 ---------------------------
__global__ __launch_bounds__(256) void logsoftmax_kernel(
    const float* __restrict__ X, float* __restrict__ Y)
{
    __shared__ float redm[8];
    __shared__ float reds[8];
    int row = blockIdx.x;
    int tid = threadIdx.x;

    float4 x = reinterpret_cast<const float4*>(X + (size_t)row * VV)[tid];

    // max
    float m = fmaxf(fmaxf(x.x, x.y), fmaxf(x.z, x.w));
    #pragma unroll
    for (int o = 16; o; o >>= 1) m = fmaxf(m, __shfl_xor_sync(0xffffffffu, m, o));
    if ((tid & 31) == 0) redm[tid >> 5] = m;
    __syncthreads();
    float mx = redm[0];
    #pragma unroll
    for (int i = 1; i < 8; ++i) mx = fmaxf(mx, redm[i]);

    // sum of exp
    float s = expf(x.x - mx) + expf(x.y - mx) + expf(x.z - mx) + expf(x.w - mx);
    #pragma unroll
    for (int o = 16; o; o >>= 1) s += __shfl_xor_sync(0xffffffffu, s, o);
    if ((tid & 31) == 0) reds[tid >> 5] = s;
    __syncthreads();
    float sum = 0.f;
    #pragma unroll
    for (int i = 0; i < 8; ++i) sum += reds[i];

    float lse = mx + logf(sum);
    float4 y = make_float4(x.x - lse, x.y - lse, x.z - lse, x.w - lse);
    reinterpret_cast<float4*>(Y + (size_t)row * VV)[tid] = y;
}

// ---------------- enc_lens passthrough --------------------------------------
__global__ void lens_kernel(const int* __restrict__ flen, float* __restrict__ out) {
    int i = threadIdx.x;
    if (i < BB) out[i] = (float)flen[i];
}

// ---------------- launch -----------------------------------------------------
extern "C" void kernel_launch(void* const* d_in, const int* in_sizes, int n_in,
                              void* d_out, int out_size)
{
    const float* encoder_out = (const float*)d_in[0];
    const int*   features_len= (const int*)  d_in[1];
    const int*   targets     = (const int*)  d_in[2];
    const float* W_enc = (const float*)d_in[3];
    const float* b_enc = (const float*)d_in[4];
    const float* emb   = (const float*)d_in[5];
    const float* W_p1  = (const float*)d_in[6];
    const float* b_p1  = (const float*)d_in[7];
    const float* W_p2  = (const float*)d_in[8];
    const float* b_p2  = (const float*)d_in[9];
    const float* W_po  = (const float*)d_in[10];
    const float* b_po  = (const float*)d_in[11];
    const float* W_j1  = (const float*)d_in[12];
    const float* b_j1  = (const float*)d_in[13];
    const float* W_j2  = (const float*)d_in[14];
    const float* b_j2  = (const float*)d_in[15];

    float *enc, *pred, *logits, *buf1, *buf2;
    int2* ctx;
    cudaGetSymbolAddress((void**)&enc,    g_enc);
    cudaGetSymbolAddress((void**)&pred,   g_pred);
    cudaGetSymbolAddress((void**)&logits, g_logits);
    cudaGetSymbolAddress((void**)&buf1,   g_buf1);
    cudaGetSymbolAddress((void**)&buf2,   g_buf2);
    cudaGetSymbolAddress((void**)&ctx,    g_ctx);

    float* out = (float*)d_out;
    float* out_log  = out;                                  // log_probs
    float* out_pred = out + (size_t)MM * VV;                // pred_log_probs
    float* out_enc  = out + 2 * (size_t)MM * VV;            // enc_log_probs
    float* out_lens = out + 3 * (size_t)MM * VV;            // enc_lens (as float)

    // 1. viterbi context
    ctx_kernel<<<1, 32>>>(targets);

    // 2. enc = encoder_out @ W_enc + b_enc           [32000,512]@[512,1024]
    {
        dim3 grid(VV / 128, MM / 128);
        sgemm_kernel<0,0><<<grid, 256>>>(encoder_out, nullptr, nullptr, nullptr,
                                         W_enc, b_enc, enc, MM, VV, DENC);
    }
    // 3. a1 = tanh(gather(emb,ctx) @ W_p1 + b_p1)    [32000,512]@[512,640]
    {
        dim3 grid(PP / 128, MM / 128);
        sgemm_kernel<1,1><<<grid, 256>>>(nullptr, nullptr, ctx, emb,
                                         W_p1, b_p1, buf1, MM, PP, 2 * EE);
    }
    // 4. a2 = tanh(a1 @ W_p2 + b_p2)                 [32000,640]@[640,640]
    {
        dim3 grid(PP / 128, MM / 128);
        sgemm_kernel<0,1><<<grid, 256>>>(buf1, nullptr, nullptr, nullptr,
                                         W_p2, b_p2, buf2, MM, PP, PP);
    }
    // 5. pred = a2 @ W_po + b_po                     [32000,640]@[640,1024]
    {
        dim3 grid(VV / 128, MM / 128);
        sgemm_kernel<0,0><<<grid, 256>>>(buf2, nullptr, nullptr, nullptr,
                                         W_po, b_po, pred, MM, VV, PP);
    }
    // 6. h = tanh((enc+pred) @ W_j1 + b_j1)          [32000,1024]@[1024,640]
    {
        dim3 grid(JJ / 128, MM / 128);
        sgemm_kernel<2,1><<<grid, 256>>>(enc, pred, nullptr, nullptr,
                                         W_j1, b_j1, buf1, MM, JJ, VV);
    }
    // 7. logits = h @ W_j2 + b_j2                    [32000,640]@[640,1024]
    {
        dim3 grid(VV / 128, MM / 128);
        sgemm_kernel<0,0><<<grid, 256>>>(buf1, nullptr, nullptr, nullptr,
                                         W_j2, b_j2, logits, MM, VV, JJ);
    }

    // 8. log-softmaxes
    logsoftmax_kernel<<<MM, 256>>>(logits, out_log);
    logsoftmax_kernel<<<MM, 256>>>(pred,   out_pred);
    logsoftmax_kernel<<<MM, 256>>>(enc,    out_enc);

    // 9. enc_lens
    lens_kernel<<<1, 32>>>(features_len, out_lens);
}

// round 3
// speedup vs baseline: 5.1139x; 5.1139x over previous
#include <cuda_runtime.h>
#include <math.h>
#include <stdint.h>

// ---------------- arch feature gate ----------------
// tcgen05 only exists in the arch-specific (compute_103a) pass. The harness
// also compiles a compute_103 PTX pass, which must see a fallback.
#if !defined(__CUDA_ARCH__) || defined(__CUDA_ARCH_FEAT_SM103_ALL) || \
    defined(__CUDA_ARCH_FEAT_SM100_ALL) || defined(__CUDA_ARCH_FEAT_SM101_ALL) || \
    defined(__CUDA_ARCH_FEAT_SM110_ALL)
#define HAS_TC 1
#else
#define HAS_TC 0
#endif

// ---------------- problem constants ----------------
#define BB 16
#define TT 2000
#define MM (BB*TT)        // 32000
#define DENC 512
#define VV 1024
#define EE 256
#define PP 640
#define JJ 640

#define BM 128
#define BK 32
#define NS 4

// ---------------- scratch (device globals) ----------------
__device__ float g_enc[(size_t)MM * VV];
__device__ float g_pred[(size_t)MM * VV];
__device__ float g_sum[(size_t)MM * VV];
__device__ float g_logits[(size_t)MM * VV];
__device__ float g_b1[(size_t)MM * PP];
__device__ float g_b2[(size_t)MM * PP];
__device__ float g_wt[4u * 1024u * 1024u];
__device__ int2  g_ctx[MM];

// transposed-weight offsets (floats)
#define O_ENC 0
#define O_P1  524288
#define O_P2  851968
#define O_PO  1261568
#define O_J1  1916928
#define O_J2  2572288

// ---------------- generic PTX helpers ----------------
__device__ __forceinline__ uint32_t smem_u32(const void* p) {
    uint32_t a;
    asm("{ .reg .u64 t; cvta.to.shared.u64 t, %1; cvt.u32.u64 %0, t; }" : "=r"(a) : "l"(p));
    return a;
}
#define SWZ(b) ((b) ^ (((b) >> 3) & 0x70))

#if HAS_TC
__device__ __forceinline__ uint32_t elect1() {
    uint32_t p;
    asm volatile("{\n\t.reg .pred p;\n\telect.sync _|p, 0xFFFFFFFF;\n\tselp.b32 %0, 1, 0, p;\n\t}" : "=r"(p));
    return p;
}
__device__ __forceinline__ uint64_t make_desc(uint32_t addr) {
    return ((uint64_t)((addr >> 4) & 0x3FFF))
         | (1ull << 16)       // LBO = 1 (16B)
         | (64ull << 32)      // SBO = 64 (1024B per 8-row group)
         | (1ull << 46)       // version = 1 (Blackwell)
         | (2ull << 61);      // SW128
}
__device__ __forceinline__ void cp16(uint32_t s, const void* g) {
    asm volatile("cp.async.cg.shared.global [%0], [%1], 16;\n" :: "r"(s), "l"(g));
}
#define CP_COMMIT() asm volatile("cp.async.commit_group;\n" ::: "memory")
#define CP_WAIT3()  asm volatile("cp.async.wait_group 3;\n" ::: "memory")

__device__ __forceinline__ void mbar_init(uint32_t a, uint32_t cnt) {
    asm volatile("mbarrier.init.shared.b64 [%0], %1;" :: "r"(a), "r"(cnt) : "memory");
}
__device__ __forceinline__ void mbar_wait(uint32_t a, uint32_t parity) {
    uint32_t done = 0;
    while (!done) {
        asm volatile("{\n\t.reg .pred p;\n\t"
            "mbarrier.try_wait.parity.acquire.cta.shared::cta.b64 p, [%1], %2, 0x989680;\n\t"
            "selp.b32 %0, 1, 0, p;\n\t}"
            : "=r"(done) : "r"(a), "r"(parity) : "memory");
    }
}
__device__ __forceinline__ void tc_alloc(uint32_t slot, uint32_t ncols) {
    asm volatile("tcgen05.alloc.cta_group::1.sync.aligned.shared::cta.b32 [%0], %1;"
                 :: "r"(slot), "r"(ncols) : "memory");
}
__device__ __forceinline__ void tc_dealloc(uint32_t tmem, uint32_t ncols) {
    asm volatile("tcgen05.dealloc.cta_group::1.sync.aligned.b32 %0, %1;" :: "r"(tmem), "r"(ncols));
}
__device__ __forceinline__ void tc_relinq() {
    asm volatile("tcgen05.relinquish_alloc_permit.cta_group::1.sync.aligned;");
}
__device__ __forceinline__ void tc_commit(uint32_t mbar) {
    asm volatile("tcgen05.commit.cta_group::1.mbarrier::arrive::one.shared::cluster.b64 [%0];"
                 :: "r"(mbar) : "memory");
}
__device__ __forceinline__ void mma_tf32_ss(uint32_t d, uint64_t ad, uint64_t bd,
                                            uint32_t idesc, uint32_t en) {
    asm volatile(
        "{\n\t.reg .pred p;\n\tsetp.ne.u32 p, %4, 0;\n\t"
        "tcgen05.mma.cta_group::1.kind::tf32 [%0], %1, %2, %3, p;\n\t}"
        :: "r"(d), "l"(ad), "l"(bd), "r"(idesc), "r"(en) : "memory");
}
__device__ __forceinline__ void ldtm32(uint32_t* r, uint32_t a) {
    asm volatile(
        "tcgen05.ld.sync.aligned.32x32b.x32.b32 "
        "{%0, %1, %2, %3, %4, %5, %6, %7, %8, %9, %10, %11, %12, %13, %14, %15, "
        " %16, %17, %18, %19, %20, %21, %22, %23, %24, %25, %26, %27, %28, %29, %30, %31}, [%32];"
        : "=r"(r[0]), "=r"(r[1]), "=r"(r[2]), "=r"(r[3]), "=r"(r[4]), "=r"(r[5]), "=r"(r[6]), "=r"(r[7]),
          "=r"(r[8]), "=r"(r[9]), "=r"(r[10]), "=r"(r[11]), "=r"(r[12]), "=r"(r[13]), "=r"(r[14]), "=r"(r[15]),
          "=r"(r[16]), "=r"(r[17]), "=r"(r[18]), "=r"(r[19]), "=r"(r[20]), "=r"(r[21]), "=r"(r[22]), "=r"(r[23]),
          "=r"(r[24]), "=r"(r[25]), "=r"(r[26]), "=r"(r[27]), "=r"(r[28]), "=r"(r[29]), "=r"(r[30]), "=r"(r[31])
        : "r"(a));
}
#define TC_WAIT_LD()  asm volatile("tcgen05.wait::ld.sync.aligned;" ::: "memory")
#define TC_FENCE_AFTER()  asm volatile("tcgen05.fence::after_thread_sync;" ::: "memory")
#define TC_FENCE_BEFORE() asm volatile("tcgen05.fence::before_thread_sync;" ::: "memory")
#endif  // HAS_TC

// ---------------- weight transpose (+ tf32 rna rounding) ----------------
__global__ void transpose_kernel(const float* __restrict__ W, float* __restrict__ Wt,
                                 int K, int N) {
    __shared__ float tile[32][33];
    int n0 = blockIdx.x * 32, k0 = blockIdx.y * 32;
    int tx = threadIdx.x, ty = threadIdx.y;  // (32, 8)
    #pragma unroll
    for (int i = 0; i < 32; i += 8)
        tile[ty + i][tx] = W[(size_t)(k0 + ty + i) * N + n0 + tx];
    __syncthreads();
    #pragma unroll
    for (int i = 0; i < 32; i += 8) {
        float v = tile[tx][ty + i];
        uint32_t u;
        asm("cvt.rna.tf32.f32 %0, %1;" : "=r"(u) : "f"(v));
        Wt[(size_t)(n0 + ty + i) * K + k0 + tx] = __uint_as_float(u);
    }
}

// ---------------- viterbi context (parallel cummax scan) ----------------
__global__ void ctx_kernel(const int* __restrict__ targets) {
    __shared__ int pmax[2048];
    __shared__ int tot[256];
    int b = blockIdx.x;
    const int* tg = targets + (size_t)b * TT;
    int tid = threadIdx.x;

    int loc[8];
    int run = -1;
    #pragma unroll
    for (int j = 0; j < 8; ++j) {
        int t = tid * 8 + j;
        int p = (t < TT && tg[t] != 0) ? t : -1;
        run = max(run, p);
        loc[j] = run;
    }
    tot[tid] = run;
    __syncthreads();
    if (tid == 0) {
        int r = -1;
        for (int i = 0; i < 256; ++i) { int v = tot[i]; tot[i] = r; r = max(r, v); }
    }
    __syncthreads();
    int off = tot[tid];
    #pragma unroll
    for (int j = 0; j < 8; ++j) pmax[tid * 8 + j] = max(off, loc[j]);
    __syncthreads();

    for (int t = tid; t < TT; t += 256) {
        int p1 = (t >= 1) ? pmax[t - 1] : -1;
        int p2 = (t >= 2) ? pmax[t - 2] : -1;
        int c0 = (p1 >= 0) ? tg[p1] : 0;
        int c1 = (p2 >= 0) ? tg[p2] : 0;
        g_ctx[(size_t)b * TT + t] = make_int2(c0, c1);
    }
}

// ---------------- GEMM: C = act(A @ Bt^T + bias) ----------------
// Bt is [N,K] row-major (pre-transposed, tf32-rounded).
// ASRC: 0 = A[M,K]; 1 = gather from emb via g_ctx (K=512, halves of 256).
// ACT:  0 = none, 1 = tanh.  FUSE: also write Csum = C + Cadd.
template<int BN, int ASRC, int ACT, int FUSE>
__global__ __launch_bounds__(256) void mma_gemm(
    const float* __restrict__ A, const float* __restrict__ emb,
    const float* __restrict__ Bt, const float* __restrict__ bias,
    float* __restrict__ C, const float* __restrict__ Cadd, float* __restrict__ Csum,
    int K, int ldc)
{
#if HAS_TC
    // ======== tcgen05 tf32 path (sm_103a cubin) ========
    extern __shared__ char smem[];
    const uint32_t sbase = smem_u32(smem);
    const int tid = threadIdx.x;
    const int wid = tid >> 5;
    const int lane = tid & 31;
    const int gRow = blockIdx.x * BM;
    const int ncol0 = blockIdx.y * BN;
    const float* BtT = Bt + (size_t)ncol0 * K;

    const uint32_t ctrl = sbase;                       // tmem ptr
    const uint32_t mb   = sbase + 16;                  // NS mbarriers
    const uint32_t tile0 = (sbase + 1024 + 1023) & ~1023u;  // 1024B-aligned tiles
    const int STAGE = (BM + BN) * BK * 4;
    const uint32_t NCOLS = (BN <= 128) ? 128u : 256u;

    if (wid == 0) tc_alloc(ctrl, NCOLS);
    if (tid == 0) { for (int s = 0; s < NS; s++) mbar_init(mb + 8 * s, 1); }
    __syncthreads();
    uint32_t tmem;
    asm volatile("ld.shared.b32 %0, [%1];" : "=r"(tmem) : "r"(ctrl));

    int2 cxr[4];
    if (ASRC == 1) {
        #pragma unroll
        for (int t = 0; t < 4; t++) cxr[t] = g_ctx[gRow + ((tid + t * 256) >> 3)];
    }

    const int KT = K / BK;

    auto load_stage = [&](int ki, int s) {
        const int k0 = ki * BK;
        const uint32_t ab = tile0 + s * STAGE;
        const uint32_t bb = ab + BM * BK * 4;
        #pragma unroll
        for (int t = 0; t < 4; t++) {
            int q = tid + t * 256, r = q >> 3, cv = (q & 7) * 4;
            const float* gp;
            if (ASRC == 1) {
                int idx = (k0 < 256) ? cxr[t].x : cxr[t].y;
                gp = emb + (size_t)idx * EE + ((k0 & 255) + cv);
            } else {
                gp = A + (size_t)(gRow + r) * K + (k0 + cv);
            }
            cp16(ab + SWZ(r * 128 + cv * 4), gp);
        }
        #pragma unroll
        for (int t = 0; t < BN / 32; t++) {
            int q = tid + t * 256, r = q >> 3, cv = (q & 7) * 4;
            cp16(bb + SWZ(r * 128 + cv * 4), BtT + (size_t)r * K + (k0 + cv));
        }
    };

    #pragma unroll
    for (int i = 0; i < NS; i++) { load_stage(i, i); CP_COMMIT(); }

    const uint32_t idesc = (1u << 4) | (2u << 7) | (2u << 10)
                         | ((uint32_t)(BN / 8) << 17) | ((uint32_t)(BM / 16) << 24);

    for (int i = 0; i < KT; i++) {
        const int s = i & (NS - 1);
        CP_WAIT3();
        __syncthreads();
        if (wid == 0) {
            asm volatile("fence.proxy.async.shared::cta;" ::: "memory");
            TC_FENCE_AFTER();
            if (elect1()) {
                const uint32_t ab = tile0 + s * STAGE;
                const uint32_t bb = ab + BM * BK * 4;
                uint64_t ad = make_desc(ab), bd = make_desc(bb);
                #pragma unroll
                for (int kk = 0; kk < 4; kk++)
                    mma_tf32_ss(tmem, ad + kk * 2, bd + kk * 2, idesc, (i | kk) ? 1u : 0u);
                tc_commit(mb + 8 * s);
            }
        }
        if (i + NS < KT) {
            mbar_wait(mb + 8 * s, (i / NS) & 1);
            load_stage(i + NS, s);
        }
        CP_COMMIT();
    }
    {
        const int last = KT - 1, ls = last & (NS - 1);
        mbar_wait(mb + 8 * ls, (last / NS) & 1);
    }
    TC_FENCE_AFTER();
    __syncthreads();

    // ---- epilogue: warps 0-3 read TMEM; bias + act + store (+ fused sum) ----
    if (wid < 4) {
        const int row = gRow + wid * 32 + lane;
        float* crow = C + (size_t)row * ldc + ncol0;
        const float* bs = bias + ncol0;
        const float* erow = FUSE ? (Cadd + (size_t)row * ldc + ncol0) : nullptr;
        float* srow = FUSE ? (Csum + (size_t)row * ldc + ncol0) : nullptr;
        #pragma unroll
        for (int c0 = 0; c0 < BN; c0 += 32) {
            uint32_t r[32];
            ldtm32(r, tmem + c0);
            TC_WAIT_LD();
            #pragma unroll
            for (int j = 0; j < 32; j += 4) {
                float4 b4 = *reinterpret_cast<const float4*>(bs + c0 + j);
                float4 o;
                o.x = __uint_as_float(r[j + 0]) + b4.x;
                o.y = __uint_as_float(r[j + 1]) + b4.y;
                o.z = __uint_as_float(r[j + 2]) + b4.z;
                o.w = __uint_as_float(r[j + 3]) + b4.w;
                if (ACT) { o.x = tanhf(o.x); o.y = tanhf(o.y); o.z = tanhf(o.z); o.w = tanhf(o.w); }
                *reinterpret_cast<float4*>(crow + c0 + j) = o;
                if (FUSE) {
                    float4 e4 = *reinterpret_cast<const float4*>(erow + c0 + j);
                    float4 s4 = make_float4(o.x + e4.x, o.y + e4.y, o.z + e4.z, o.w + e4.w);
                    *reinterpret_cast<float4*>(srow + c0 + j) = s4;
                }
            }
        }
        TC_FENCE_BEFORE();
    }
    __syncthreads();
    if (wid == 0) {
        tc_relinq();
        tc_dealloc(tmem, NCOLS);
    }
#else
    // ======== FFMA fallback (compute_103 PTX pass; not selected at runtime) ========
    __shared__ float As[8][128];
    __shared__ float Bs[8][128];
    const int tid = threadIdx.x;
    const int tx = tid & 15, ty = tid >> 4;
    const int gRow = blockIdx.x * BM;
    const int ncol0 = blockIdx.y * BN;
    const float* BtT = Bt + (size_t)ncol0 * K;

    for (int nc = 0; nc < BN; nc += 128) {
        float acc[8][8];
        #pragma unroll
        for (int i = 0; i < 8; ++i)
            #pragma unroll
            for (int j = 0; j < 8; ++j) acc[i][j] = 0.f;

        for (int k0 = 0; k0 < K; k0 += 8) {
            int rowA = tid >> 1, colA = (tid & 1) * 4;
            float4 av;
            int m = gRow + rowA;
            if (ASRC == 1) {
                int2 cx = g_ctx[m];
                int k = k0 + colA;
                int idx = (k < 256) ? cx.x : cx.y;
                av = *reinterpret_cast<const float4*>(emb + (size_t)idx * EE + (k & 255));
            } else {
                av = *reinterpret_cast<const float4*>(A + (size_t)m * K + k0 + colA);
            }
            As[colA + 0][rowA] = av.x; As[colA + 1][rowA] = av.y;
            As[colA + 2][rowA] = av.z; As[colA + 3][rowA] = av.w;

            int nB = tid >> 1, kB = (tid & 1) * 4;
            float4 bv = *reinterpret_cast<const float4*>(BtT + (size_t)(nc + nB) * K + k0 + kB);
            Bs[kB + 0][nB] = bv.x; Bs[kB + 1][nB] = bv.y;
            Bs[kB + 2][nB] = bv.z; Bs[kB + 3][nB] = bv.w;
            __syncthreads();

            #pragma unroll
            for (int kk = 0; kk < 8; ++kk) {
                float ar[8], br[8];
                #pragma unroll
                for (int i = 0; i < 8; ++i) ar[i] = As[kk][ty * 8 + i];
                #pragma unroll
                for (int j = 0; j < 8; ++j) br[j] = Bs[kk][tx * 8 + j];
                #pragma unroll
                for (int i = 0; i < 8; ++i)
                    #pragma unroll
                    for (int j = 0; j < 8; ++j)
                        acc[i][j] = fmaf(ar[i], br[j], acc[i][j]);
            }
            __syncthreads();
        }

        #pragma unroll
        for (int i = 0; i < 8; ++i) {
            int row = gRow + ty * 8 + i;
            int col = ncol0 + nc + tx * 8;
            #pragma unroll
            for (int j = 0; j < 8; ++j) {
                float o = acc[i][j] + bias[col + j];
                if (ACT) o = tanhf(o);
                C[(size_t)row * ldc + col + j] = o;
                if (FUSE)
                    Csum[(size_t)row * ldc + col + j] = o + Cadd[(size_t)row * ldc + col + j];
            }
        }
    }
#endif
}

// ---------------- row-wise log-softmax over V=1024 ----------------
__global__ __launch_bounds__(256) void logsoftmax_kernel(
    const float* __restrict__ X, float* __restrict__ Y)
{
    __shared__ float redm[8];
    __shared__ float reds[8];
    int row = blockIdx.x;
    int tid = threadIdx.x;

    float4 x = reinterpret_cast<const float4*>(X + (size_t)row * VV)[tid];

    float m = fmaxf(fmaxf(x.x, x.y), fmaxf(x.z, x.w));
    #pragma unroll
    for (int o = 16; o; o >>= 1) m = fmaxf(m, __shfl_xor_sync(0xffffffffu, m, o));
    if ((tid & 31) == 0) redm[tid >> 5] = m;
    __syncthreads();
    float mx = redm[0];
    #pragma unroll
    for (int i = 1; i < 8; ++i) mx = fmaxf(mx, redm[i]);

    float s = expf(x.x - mx) + expf(x.y - mx) + expf(x.z - mx) + expf(x.w - mx);
    #pragma unroll
    for (int o = 16; o; o >>= 1) s += __shfl_xor_sync(0xffffffffu, s, o);
    if ((tid & 31) == 0) reds[tid >> 5] = s;
    __syncthreads();
    float sum = 0.f;
    #pragma unroll
    for (int i = 0; i < 8; ++i) sum += reds[i];

    float lse = mx + logf(sum);
    float4 y = make_float4(x.x - lse, x.y - lse, x.z - lse, x.w - lse);
    reinterpret_cast<float4*>(Y + (size_t)row * VV)[tid] = y;
}

__global__ void lens_kernel(const int* __restrict__ flen, float* __restrict__ out) {
    int i = threadIdx.x;
    if (i < BB) out[i] = (float)flen[i];
}

// ---------------- launch ----------------
extern "C" void kernel_launch(void* const* d_in, const int* in_sizes, int n_in,
                              void* d_out, int out_size)
{
    const float* encoder_out  = (const float*)d_in[0];
    const int*   features_len = (const int*)  d_in[1];
    const int*   targets      = (const int*)  d_in[2];
    const float* W_enc = (const float*)d_in[3];
    const float* b_enc = (const float*)d_in[4];
    const float* emb   = (const float*)d_in[5];
    const float* W_p1  = (const float*)d_in[6];
    const float* b_p1  = (const float*)d_in[7];
    const float* W_p2  = (const float*)d_in[8];
    const float* b_p2  = (const float*)d_in[9];
    const float* W_po  = (const float*)d_in[10];
    const float* b_po  = (const float*)d_in[11];
    const float* W_j1  = (const float*)d_in[12];
    const float* b_j1  = (const float*)d_in[13];
    const float* W_j2  = (const float*)d_in[14];
    const float* b_j2  = (const float*)d_in[15];

    float *enc, *pred, *sum, *logits, *b1, *b2, *wt;
    cudaGetSymbolAddress((void**)&enc,    g_enc);
    cudaGetSymbolAddress((void**)&pred,   g_pred);
    cudaGetSymbolAddress((void**)&sum,    g_sum);
    cudaGetSymbolAddress((void**)&logits, g_logits);
    cudaGetSymbolAddress((void**)&b1,     g_b1);
    cudaGetSymbolAddress((void**)&b2,     g_b2);
    cudaGetSymbolAddress((void**)&wt,     g_wt);

    float* out = (float*)d_out;
    float* out_log  = out;
    float* out_pred = out + (size_t)MM * VV;
    float* out_enc  = out + 2 * (size_t)MM * VV;
    float* out_lens = out + 3 * (size_t)MM * VV;

    const int S256 = 2048 + NS * (BM + 256) * BK * 4;   // 198656
    const int S128 = 2048 + NS * (BM + 128) * BK * 4;   // 133120
    cudaFuncSetAttribute(mma_gemm<256,0,0,0>, cudaFuncAttributeMaxDynamicSharedMemorySize, S256);
    cudaFuncSetAttribute(mma_gemm<256,1,1,0>, cudaFuncAttributeMaxDynamicSharedMemorySize, S256);
    cudaFuncSetAttribute(mma_gemm<256,0,1,0>, cudaFuncAttributeMaxDynamicSharedMemorySize, S256);
    cudaFuncSetAttribute(mma_gemm<256,0,0,1>, cudaFuncAttributeMaxDynamicSharedMemorySize, S256);
    cudaFuncSetAttribute(mma_gemm<128,1,1,0>, cudaFuncAttributeMaxDynamicSharedMemorySize, S128);
    cudaFuncSetAttribute(mma_gemm<128,0,1,0>, cudaFuncAttributeMaxDynamicSharedMemorySize, S128);

    // 0. transpose + tf32-round all weights
    dim3 tb(32, 8);
    transpose_kernel<<<dim3(VV/32, DENC/32), tb>>>(W_enc, wt + O_ENC, DENC, VV);
    transpose_kernel<<<dim3(PP/32, DENC/32), tb>>>(W_p1,  wt + O_P1,  DENC, PP);
    transpose_kernel<<<dim3(PP/32, PP/32),   tb>>>(W_p2,  wt + O_P2,  PP,   PP);
    transpose_kernel<<<dim3(VV/32, PP/32),   tb>>>(W_po,  wt + O_PO,  PP,   VV);
    transpose_kernel<<<dim3(JJ/32, VV/32),   tb>>>(W_j1,  wt + O_J1,  VV,   JJ);
    transpose_kernel<<<dim3(VV/32, JJ/32),   tb>>>(W_j2,  wt + O_J2,  JJ,   VV);

    // 1. viterbi context
    ctx_kernel<<<BB, 256>>>(targets);

    const int MT = MM / BM;  // 250

    // 2. enc = encoder_out @ W_enc + b_enc          [32000,512] -> [32000,1024]
    mma_gemm<256,0,0,0><<<dim3(MT, 4), 256, S256>>>(
        encoder_out, nullptr, wt + O_ENC, b_enc, enc, nullptr, nullptr, DENC, VV);

    // 3. a1 = tanh(gather(emb,ctx) @ W_p1 + b_p1)   -> [32000,640]
    mma_gemm<256,1,1,0><<<dim3(MT, 2), 256, S256>>>(
        nullptr, emb, wt + O_P1, b_p1, b1, nullptr, nullptr, DENC, PP);
    mma_gemm<128,1,1,0><<<dim3(MT, 1), 256, S128>>>(
        nullptr, emb, wt + O_P1 + (size_t)512 * DENC, b_p1 + 512, b1 + 512,
        nullptr, nullptr, DENC, PP);

    // 4. a2 = tanh(a1 @ W_p2 + b_p2)                -> [32000,640]
    mma_gemm<256,0,1,0><<<dim3(MT, 2), 256, S256>>>(
        b1, nullptr, wt + O_P2, b_p2, b2, nullptr, nullptr, PP, PP);
    mma_gemm<128,0,1,0><<<dim3(MT, 1), 256, S128>>>(
        b1, nullptr, wt + O_P2 + (size_t)512 * PP, b_p2 + 512, b2 + 512,
        nullptr, nullptr, PP, PP);

    // 5. pred = a2 @ W_po + b_po ; sum = enc + pred -> [32000,1024]
    mma_gemm<256,0,0,1><<<dim3(MT, 4), 256, S256>>>(
        b2, nullptr, wt + O_PO, b_po, pred, enc, sum, PP, VV);

    // 6. h = tanh(sum @ W_j1 + b_j1)                -> [32000,640]
    mma_gemm<256,0,1,0><<<dim3(MT, 2), 256, S256>>>(
        sum, nullptr, wt + O_J1, b_j1, b1, nullptr, nullptr, VV, JJ);
    mma_gemm<128,0,1,0><<<dim3(MT, 1), 256, S128>>>(
        sum, nullptr, wt + O_J1 + (size_t)512 * VV, b_j1 + 512, b1 + 512,
        nullptr, nullptr, VV, JJ);

    // 7. logits = h @ W_j2 + b_j2                   -> [32000,1024]
    mma_gemm<256,0,0,0><<<dim3(MT, 4), 256, S256>>>(
        b1, nullptr, wt + O_J2, b_j2, logits, nullptr, nullptr, JJ, VV);

    // 8. log-softmaxes
    logsoftmax_kernel<<<MM, 256>>>(logits, out_log);
    logsoftmax_kernel<<<MM, 256>>>(pred,   out_pred);
    logsoftmax_kernel<<<MM, 256>>>(enc,    out_enc);

    // 9. enc_lens
    lens_kernel<<<1, 32>>>(features_len, out_lens);
}

// round 4
// speedup vs baseline: 5.1456x; 1.0062x over previous
#include <cuda_runtime.h>
#include <cuda_bf16.h>
#include <math.h>
#include <stdint.h>

// ---------------- arch feature gate ----------------
#if !defined(__CUDA_ARCH__) || defined(__CUDA_ARCH_FEAT_SM103_ALL) || \
    defined(__CUDA_ARCH_FEAT_SM100_ALL) || defined(__CUDA_ARCH_FEAT_SM101_ALL) || \
    defined(__CUDA_ARCH_FEAT_SM110_ALL)
#define HAS_TC 1
#else
#define HAS_TC 0
#endif

// ---------------- problem constants ----------------
#define BB 16
#define TT 2000
#define MM (BB*TT)        // 32000
#define DENC 512
#define VV 1024
#define EE 256
#define PP 640
#define JJ 640

#define BM 128
#define BK 64             // K elements per chunk (128 bytes bf16 = SW128 row)

// ---------------- scratch (device globals) ----------------
__device__ float g_enc[(size_t)MM * VV];
__device__ float g_pred[(size_t)MM * VV];
__device__ float g_logits[(size_t)MM * VV];
__device__ __nv_bfloat16 g_hsum[(size_t)MM * VV];
__device__ __nv_bfloat16 g_hb1[(size_t)MM * PP];
__device__ __nv_bfloat16 g_hb2[(size_t)MM * PP];
__device__ __nv_bfloat16 g_encbf[(size_t)MM * DENC];
__device__ __nv_bfloat16 g_embbf[(size_t)VV * EE];
__device__ __nv_bfloat16 g_wt[4u * 1024u * 1024u];
__device__ int2  g_ctx[MM];

// transposed-weight offsets (elements)
#define O_ENC 0
#define O_P1  524288
#define O_P2  851968
#define O_PO  1261568
#define O_J1  1916928
#define O_J2  2572288

// ---------------- generic PTX helpers ----------------
__device__ __forceinline__ uint32_t smem_u32(const void* p) {
    uint32_t a;
    asm("{ .reg .u64 t; cvta.to.shared.u64 t, %1; cvt.u32.u64 %0, t; }" : "=r"(a) : "l"(p));
    return a;
}
#define SWZ(b) ((b) ^ (((b) >> 3) & 0x70))

#if HAS_TC
__device__ __forceinline__ uint32_t elect1() {
    uint32_t p;
    asm volatile("{\n\t.reg .pred p;\n\telect.sync _|p, 0xFFFFFFFF;\n\tselp.b32 %0, 1, 0, p;\n\t}" : "=r"(p));
    return p;
}
__device__ __forceinline__ uint64_t make_desc(uint32_t addr) {
    return ((uint64_t)((addr >> 4) & 0x3FFF))
         | (1ull << 16)       // LBO = 1 (16B)
         | (64ull << 32)      // SBO = 64 (1024B per 8-row group)
         | (1ull << 46)       // version = 1 (Blackwell)
         | (2ull << 61);      // SW128
}
__device__ __forceinline__ void cp16(uint32_t s, const void* g) {
    asm volatile("cp.async.cg.shared.global [%0], [%1], 16;\n" :: "r"(s), "l"(g));
}
#define CP_COMMIT() asm volatile("cp.async.commit_group;\n" ::: "memory")

__device__ __forceinline__ void mbar_init(uint32_t a, uint32_t cnt) {
    asm volatile("mbarrier.init.shared.b64 [%0], %1;" :: "r"(a), "r"(cnt) : "memory");
}
__device__ __forceinline__ void mbar_wait(uint32_t a, uint32_t parity) {
    uint32_t done = 0;
    while (!done) {
        asm volatile("{\n\t.reg .pred p;\n\t"
            "mbarrier.try_wait.parity.acquire.cta.shared::cta.b64 p, [%1], %2, 0x989680;\n\t"
            "selp.b32 %0, 1, 0, p;\n\t}"
            : "=r"(done) : "r"(a), "r"(parity) : "memory");
    }
}
__device__ __forceinline__ void tc_alloc(uint32_t slot, uint32_t ncols) {
    asm volatile("tcgen05.alloc.cta_group::1.sync.aligned.shared::cta.b32 [%0], %1;"
                 :: "r"(slot), "r"(ncols) : "memory");
}
__device__ __forceinline__ void tc_dealloc(uint32_t tmem, uint32_t ncols) {
    asm volatile("tcgen05.dealloc.cta_group::1.sync.aligned.b32 %0, %1;" :: "r"(tmem), "r"(ncols));
}
__device__ __forceinline__ void tc_relinq() {
    asm volatile("tcgen05.relinquish_alloc_permit.cta_group::1.sync.aligned;");
}
__device__ __forceinline__ void tc_commit(uint32_t mbar) {
    asm volatile("tcgen05.commit.cta_group::1.mbarrier::arrive::one.shared::cluster.b64 [%0];"
                 :: "r"(mbar) : "memory");
}
__device__ __forceinline__ void mma_bf16_ss(uint32_t d, uint64_t ad, uint64_t bd,
                                            uint32_t idesc, uint32_t en) {
    asm volatile(
        "{\n\t.reg .pred p;\n\tsetp.ne.u32 p, %4, 0;\n\t"
        "tcgen05.mma.cta_group::1.kind::f16 [%0], %1, %2, %3, p;\n\t}"
        :: "r"(d), "l"(ad), "l"(bd), "r"(idesc), "r"(en) : "memory");
}
__device__ __forceinline__ void ldtm32(uint32_t* r, uint32_t a) {
    asm volatile(
        "tcgen05.ld.sync.aligned.32x32b.x32.b32 "
        "{%0, %1, %2, %3, %4, %5, %6, %7, %8, %9, %10, %11, %12, %13, %14, %15, "
        " %16, %17, %18, %19, %20, %21, %22, %23, %24, %25, %26, %27, %28, %29, %30, %31}, [%32];"
        : "=r"(r[0]), "=r"(r[1]), "=r"(r[2]), "=r"(r[3]), "=r"(r[4]), "=r"(r[5]), "=r"(r[6]), "=r"(r[7]),
          "=r"(r[8]), "=r"(r[9]), "=r"(r[10]), "=r"(r[11]), "=r"(r[12]), "=r"(r[13]), "=r"(r[14]), "=r"(r[15]),
          "=r"(r[16]), "=r"(r[17]), "=r"(r[18]), "=r"(r[19]), "=r"(r[20]), "=r"(r[21]), "=r"(r[22]), "=r"(r[23]),
          "=r"(r[24]), "=r"(r[25]), "=r"(r[26]), "=r"(r[27]), "=r"(r[28]), "=r"(r[29]), "=r"(r[30]), "=r"(r[31])
        : "r"(a));
}
#define TC_WAIT_LD()  asm volatile("tcgen05.wait::ld.sync.aligned;" ::: "memory")
#define TC_FENCE_AFTER()  asm volatile("tcgen05.fence::after_thread_sync;" ::: "memory")
#define TC_FENCE_BEFORE() asm volatile("tcgen05.fence::before_thread_sync;" ::: "memory")
#endif  // HAS_TC

// ---------------- weight transpose (fp32 [K,N] -> bf16 [N,K]) ----------------
__global__ void transpose_kernel(const float* __restrict__ W, __nv_bfloat16* __restrict__ Wt,
                                 int K, int N) {
    __shared__ float tile[32][33];
    int n0 = blockIdx.x * 32, k0 = blockIdx.y * 32;
    int tx = threadIdx.x, ty = threadIdx.y;  // (32, 8)
    #pragma unroll
    for (int i = 0; i < 32; i += 8)
        tile[ty + i][tx] = W[(size_t)(k0 + ty + i) * N + n0 + tx];
    __syncthreads();
    #pragma unroll
    for (int i = 0; i < 32; i += 8)
        Wt[(size_t)(n0 + ty + i) * K + k0 + tx] = __float2bfloat16(tile[tx][ty + i]);
}

// ---------------- fp32 -> bf16 converter ----------------
__global__ void f2bf_kernel(const float* __restrict__ s, __nv_bfloat16* __restrict__ d, int n4) {
    int i = blockIdx.x * blockDim.x + threadIdx.x;
    if (i >= n4) return;
    float4 v = reinterpret_cast<const float4*>(s)[i];
    __nv_bfloat162 p0 = __floats2bfloat162_rn(v.x, v.y);
    __nv_bfloat162 p1 = __floats2bfloat162_rn(v.z, v.w);
    reinterpret_cast<__nv_bfloat162*>(d)[i * 2]     = p0;
    reinterpret_cast<__nv_bfloat162*>(d)[i * 2 + 1] = p1;
}

// ---------------- viterbi context (parallel cummax scan) ----------------
__global__ void ctx_kernel(const int* __restrict__ targets) {
    __shared__ int pmax[2048];
    __shared__ int tot[256];
    int b = blockIdx.x;
    const int* tg = targets + (size_t)b * TT;
    int tid = threadIdx.x;

    int loc[8];
    int run = -1;
    #pragma unroll
    for (int j = 0; j < 8; ++j) {
        int t = tid * 8 + j;
        int p = (t < TT && tg[t] != 0) ? t : -1;
        run = max(run, p);
        loc[j] = run;
    }
    tot[tid] = run;
    __syncthreads();
    if (tid == 0) {
        int r = -1;
        for (int i = 0; i < 256; ++i) { int v = tot[i]; tot[i] = r; r = max(r, v); }
    }
    __syncthreads();
    int off = tot[tid];
    #pragma unroll
    for (int j = 0; j < 8; ++j) pmax[tid * 8 + j] = max(off, loc[j]);
    __syncthreads();

    for (int t = tid; t < TT; t += 256) {
        int p1 = (t >= 1) ? pmax[t - 1] : -1;
        int p2 = (t >= 2) ? pmax[t - 2] : -1;
        int c0 = (p1 >= 0) ? tg[p1] : 0;
        int c1 = (p2 >= 0) ? tg[p2] : 0;
        g_ctx[(size_t)b * TT + t] = make_int2(c0, c1);
    }
}

// ---------------- tcgen05 bf16 GEMM ----------------
// C = act(A @ Bt^T + bias). Bt [N,K] bf16 (pre-transposed).
// ASRC: 0 = A[M,K] bf16; 1 = gather from g_embbf via g_ctx (K=512).
// ACT: 0/1 tanh.
// OUTMODE: 0 = fp32 C; 1 = bf16 C; 2 = fp32 C + bf16 Csum = C + Cadd(fp32).
template<int BN, int ASRC, int ACT, int OUTMODE>
__global__ __launch_bounds__(256) void mma_gemm(
    const __nv_bfloat16* __restrict__ A, const __nv_bfloat16* __restrict__ Bt,
    const float* __restrict__ bias,
    void* __restrict__ Cv, const float* __restrict__ Cadd, __nv_bfloat16* __restrict__ Csum,
    int K, int ldc)
{
#if HAS_TC
    constexpr int NSt = (BN >= 512) ? 2 : 4;
    extern __shared__ char smem[];
    const uint32_t sbase = smem_u32(smem);
    const int tid = threadIdx.x;
    const int wid = tid >> 5;
    const int lane = tid & 31;
    const int gRow = blockIdx.x * BM;
    const int ncol0 = blockIdx.y * BN;
    const __nv_bfloat16* BtT = Bt + (size_t)ncol0 * K;

    const uint32_t ctrl = sbase;
    const uint32_t mb   = sbase + 16;
    const uint32_t tile0 = (sbase + 1024 + 1023) & ~1023u;
    const int STAGE = (BM + BN) * BK * 2;
    const uint32_t NCOLS = (BN >= 512) ? 512u : 128u;

    if (wid == 0) tc_alloc(ctrl, NCOLS);
    if (tid == 0) { for (int s = 0; s < NSt; s++) mbar_init(mb + 8 * s, 1); }
    __syncthreads();
    uint32_t tmem;
    asm volatile("ld.shared.b32 %0, [%1];" : "=r"(tmem) : "r"(ctrl));

    int2 cxr[4];
    if (ASRC == 1) {
        #pragma unroll
        for (int t = 0; t < 4; t++) cxr[t] = g_ctx[gRow + ((tid + t * 256) >> 3)];
    }

    const int KT = K / BK;
    const __nv_bfloat16* emb = g_embbf;

    auto load_stage = [&](int ki, int s) {
        const int k0 = ki * BK;
        const uint32_t ab = tile0 + s * STAGE;
        const uint32_t bb = ab + BM * BK * 2;
        // A: 128 rows x 128B = 1024 x 16B
        #pragma unroll
        for (int t = 0; t < 4; t++) {
            int q = tid + t * 256, r = q >> 3, cv = q & 7;
            const __nv_bfloat16* gp;
            if (ASRC == 1) {
                int idx = (k0 < 256) ? cxr[t].x : cxr[t].y;
                gp = emb + (size_t)idx * EE + ((k0 & 255) + cv * 8);
            } else {
                gp = A + (size_t)(gRow + r) * K + (k0 + cv * 8);
            }
            cp16(ab + SWZ(r * 128 + cv * 16), gp);
        }
        // B: BN rows x 128B
        #pragma unroll
        for (int t = 0; t < BN / 32; t++) {
            int q = tid + t * 256, r = q >> 3, cv = q & 7;
            cp16(bb + SWZ(r * 128 + cv * 16), BtT + (size_t)r * K + (k0 + cv * 8));
        }
    };

    #pragma unroll
    for (int i = 0; i < NSt; i++) { load_stage(i, i); CP_COMMIT(); }

    constexpr int NCH = (BN + 255) / 256;          // MMA N-chunks per stage
    constexpr int NC1 = (BN >= 256) ? 256 : BN;    // chunk width
    const uint32_t idesc = (1u << 4) | (1u << 7) | (1u << 10)
                         | ((uint32_t)(NC1 / 8) << 17) | ((uint32_t)(BM / 16) << 24);

    for (int i = 0; i < KT; i++) {
        const int s = i & (NSt - 1);
        if constexpr (NSt == 2) asm volatile("cp.async.wait_group 1;\n" ::: "memory");
        else                    asm volatile("cp.async.wait_group 3;\n" ::: "memory");
        __syncthreads();
        if (wid == 0) {
            asm volatile("fence.proxy.async.shared::cta;" ::: "memory");
            TC_FENCE_AFTER();
            if (elect1()) {
                const uint32_t ab = tile0 + s * STAGE;
                const uint32_t bb = ab + BM * BK * 2;
                uint64_t ad = make_desc(ab);
                #pragma unroll
                for (int c = 0; c < NCH; c++) {
                    uint64_t bd = make_desc(bb + c * (256 * 128));
                    #pragma unroll
                    for (int kk = 0; kk < 4; kk++)   // 4 x K=16 per chunk
                        mma_bf16_ss(tmem + c * 256, ad + kk * 2, bd + kk * 2, idesc,
                                    (i | kk) ? 1u : 0u);
                }
                tc_commit(mb + 8 * s);
            }
        }
        if (i + NSt < KT) {
            mbar_wait(mb + 8 * s, (i / NSt) & 1);
            load_stage(i + NSt, s);
        }
        CP_COMMIT();
    }
    {
        const int last = KT - 1, ls = last & (NSt - 1);
        mbar_wait(mb + 8 * ls, (last / NSt) & 1);
    }
    TC_FENCE_AFTER();
    __syncthreads();

    // ---- epilogue ----
    if (wid < 4) {
        const int row = gRow + wid * 32 + lane;
        const float* bs = bias + ncol0;
        float* crowf = (OUTMODE != 1) ? ((float*)Cv + (size_t)row * ldc + ncol0) : nullptr;
        __nv_bfloat16* crowh = (OUTMODE == 1) ? ((__nv_bfloat16*)Cv + (size_t)row * ldc + ncol0) : nullptr;
        const float* erow = (OUTMODE == 2) ? (Cadd + (size_t)row * ldc + ncol0) : nullptr;
        __nv_bfloat16* srow = (OUTMODE == 2) ? (Csum + (size_t)row * ldc + ncol0) : nullptr;
        #pragma unroll
        for (int c0 = 0; c0 < BN; c0 += 32) {
            uint32_t r[32];
            ldtm32(r, tmem + c0);
            TC_WAIT_LD();
            #pragma unroll
            for (int j = 0; j < 32; j += 4) {
                float4 b4 = *reinterpret_cast<const float4*>(bs + c0 + j);
                float4 o;
                o.x = __uint_as_float(r[j + 0]) + b4.x;
                o.y = __uint_as_float(r[j + 1]) + b4.y;
                o.z = __uint_as_float(r[j + 2]) + b4.z;
                o.w = __uint_as_float(r[j + 3]) + b4.w;
                if (ACT) { o.x = tanhf(o.x); o.y = tanhf(o.y); o.z = tanhf(o.z); o.w = tanhf(o.w); }
                if (OUTMODE == 1) {
                    __nv_bfloat162 p0 = __floats2bfloat162_rn(o.x, o.y);
                    __nv_bfloat162 p1 = __floats2bfloat162_rn(o.z, o.w);
                    reinterpret_cast<__nv_bfloat162*>(crowh + c0 + j)[0] = p0;
                    reinterpret_cast<__nv_bfloat162*>(crowh + c0 + j)[1] = p1;
                } else {
                    *reinterpret_cast<float4*>(crowf + c0 + j) = o;
                    if (OUTMODE == 2) {
                        float4 e4 = *reinterpret_cast<const float4*>(erow + c0 + j);
                        __nv_bfloat162 p0 = __floats2bfloat162_rn(o.x + e4.x, o.y + e4.y);
                        __nv_bfloat162 p1 = __floats2bfloat162_rn(o.z + e4.z, o.w + e4.w);
                        reinterpret_cast<__nv_bfloat162*>(srow + c0 + j)[0] = p0;
                        reinterpret_cast<__nv_bfloat162*>(srow + c0 + j)[1] = p1;
                    }
                }
            }
        }
        TC_FENCE_BEFORE();
    }
    __syncthreads();
    if (wid == 0) {
        tc_relinq();
        tc_dealloc(tmem, NCOLS);
    }
#else
    // ======== FFMA fallback (compute_103 pass; never selected at runtime) ========
    __shared__ float As[8][128];
    __shared__ float Bs[8][128];
    const int tid = threadIdx.x;
    const int tx = tid & 15, ty = tid >> 4;
    const int gRow = blockIdx.x * BM;
    const int ncol0 = blockIdx.y * BN;
    const __nv_bfloat16* BtT = Bt + (size_t)ncol0 * K;

    for (int nc = 0; nc < BN; nc += 128) {
        float acc[8][8];
        #pragma unroll
        for (int i = 0; i < 8; ++i)
            #pragma unroll
            for (int j = 0; j < 8; ++j) acc[i][j] = 0.f;

        for (int k0 = 0; k0 < K; k0 += 8) {
            int rowA = tid >> 1, colA = (tid & 1) * 4;
            int m = gRow + rowA;
            const __nv_bfloat16* ap;
            if (ASRC == 1) {
                int2 cx = g_ctx[m];
                int k = k0 + colA;
                int idx = (k < 256) ? cx.x : cx.y;
                ap = g_embbf + (size_t)idx * EE + (k & 255);
            } else {
                ap = A + (size_t)m * K + k0 + colA;
            }
            #pragma unroll
            for (int u = 0; u < 4; u++) As[colA + u][rowA] = __bfloat162float(ap[u]);

            int nB = tid >> 1, kB = (tid & 1) * 4;
            const __nv_bfloat16* bp = BtT + (size_t)(nc + nB) * K + k0 + kB;
            #pragma unroll
            for (int u = 0; u < 4; u++) Bs[kB + u][nB] = __bfloat162float(bp[u]);
            __syncthreads();

            #pragma unroll
            for (int kk = 0; kk < 8; ++kk) {
                float ar[8], br[8];
                #pragma unroll
                for (int i = 0; i < 8; ++i) ar[i] = As[kk][ty * 8 + i];
                #pragma unroll
                for (int j = 0; j < 8; ++j) br[j] = Bs[kk][tx * 8 + j];
                #pragma unroll
                for (int i = 0; i < 8; ++i)
                    #pragma unroll
                    for (int j = 0; j < 8; ++j)
                        acc[i][j] = fmaf(ar[i], br[j], acc[i][j]);
            }
            __syncthreads();
        }

        #pragma unroll
        for (int i = 0; i < 8; ++i) {
            int row = gRow + ty * 8 + i;
            int col = ncol0 + nc + tx * 8;
            #pragma unroll
            for (int j = 0; j < 8; ++j) {
                float o = acc[i][j] + bias[col + j];
                if (ACT) o = tanhf(o);
                if (OUTMODE == 1) {
                    ((__nv_bfloat16*)Cv)[(size_t)row * ldc + col + j] = __float2bfloat16(o);
                } else {
                    ((float*)Cv)[(size_t)row * ldc + col + j] = o;
                    if (OUTMODE == 2)
                        Csum[(size_t)row * ldc + col + j] =
                            __float2bfloat16(o + Cadd[(size_t)row * ldc + col + j]);
                }
            }
        }
    }
#endif
}

// ---------------- row-wise log-softmax over V=1024 ----------------
__global__ __launch_bounds__(256) void logsoftmax_kernel(
    const float* __restrict__ X, float* __restrict__ Y)
{
    __shared__ float redm[8];
    __shared__ float reds[8];
    int row = blockIdx.x;
    int tid = threadIdx.x;

    float4 x = reinterpret_cast<const float4*>(X + (size_t)row * VV)[tid];

    float m = fmaxf(fmaxf(x.x, x.y), fmaxf(x.z, x.w));
    #pragma unroll
    for (int o = 16; o; o >>= 1) m = fmaxf(m, __shfl_xor_sync(0xffffffffu, m, o));
    if ((tid & 31) == 0) redm[tid >> 5] = m;
    __syncthreads();
    float mx = redm[0];
    #pragma unroll
    for (int i = 1; i < 8; ++i) mx = fmaxf(mx, redm[i]);

    float s = expf(x.x - mx) + expf(x.y - mx) + expf(x.z - mx) + expf(x.w - mx);
    #pragma unroll
    for (int o = 16; o; o >>= 1) s += __shfl_xor_sync(0xffffffffu, s, o);
    if ((tid & 31) == 0) reds[tid >> 5] = s;
    __syncthreads();
    float sum = 0.f;
    #pragma unroll
    for (int i = 0; i < 8; ++i) sum += reds[i];

    float lse = mx + logf(sum);
    float4 y = make_float4(x.x - lse, x.y - lse, x.z - lse, x.w - lse);
    reinterpret_cast<float4*>(Y + (size_t)row * VV)[tid] = y;
}

__global__ void lens_kernel(const int* __restrict__ flen, float* __restrict__ out) {
    int i = threadIdx.x;
    if (i < BB) out[i] = (float)flen[i];
}

// ---------------- launch ----------------
extern "C" void kernel_launch(void* const* d_in, const int* in_sizes, int n_in,
                              void* d_out, int out_size)
{
    const float* encoder_out  = (const float*)d_in[0];
    const int*   features_len = (const int*)  d_in[1];
    const int*   targets      = (const int*)  d_in[2];
    const float* W_enc = (const float*)d_in[3];
    const float* b_enc = (const float*)d_in[4];
    const float* emb   = (const float*)d_in[5];
    const float* W_p1  = (const float*)d_in[6];
    const float* b_p1  = (const float*)d_in[7];
    const float* W_p2  = (const float*)d_in[8];
    const float* b_p2  = (const float*)d_in[9];
    const float* W_po  = (const float*)d_in[10];
    const float* b_po  = (const float*)d_in[11];
    const float* W_j1  = (const float*)d_in[12];
    const float* b_j1  = (const float*)d_in[13];
    const float* W_j2  = (const float*)d_in[14];
    const float* b_j2  = (const float*)d_in[15];

    float *enc, *pred, *logits;
    __nv_bfloat16 *hsum, *hb1, *hb2, *encbf, *embbf, *wt;
    cudaGetSymbolAddress((void**)&enc,    g_enc);
    cudaGetSymbolAddress((void**)&pred,   g_pred);
    cudaGetSymbolAddress((void**)&logits, g_logits);
    cudaGetSymbolAddress((void**)&hsum,   g_hsum);
    cudaGetSymbolAddress((void**)&hb1,    g_hb1);
    cudaGetSymbolAddress((void**)&hb2,    g_hb2);
    cudaGetSymbolAddress((void**)&encbf,  g_encbf);
    cudaGetSymbolAddress((void**)&embbf,  g_embbf);
    cudaGetSymbolAddress((void**)&wt,     g_wt);

    float* out = (float*)d_out;
    float* out_log  = out;
    float* out_pred = out + (size_t)MM * VV;
    float* out_enc  = out + 2 * (size_t)MM * VV;
    float* out_lens = out + 3 * (size_t)MM * VV;

    const int S512 = 2048 + 2 * (BM + 512) * BK * 2;   // 165888
    const int S128 = 2048 + 4 * (BM + 128) * BK * 2;   // 133120
    cudaFuncSetAttribute(mma_gemm<512,0,0,0>, cudaFuncAttributeMaxDynamicSharedMemorySize, S512);
    cudaFuncSetAttribute(mma_gemm<512,1,1,1>, cudaFuncAttributeMaxDynamicSharedMemorySize, S512);
    cudaFuncSetAttribute(mma_gemm<512,0,1,1>, cudaFuncAttributeMaxDynamicSharedMemorySize, S512);
    cudaFuncSetAttribute(mma_gemm<512,0,0,2>, cudaFuncAttributeMaxDynamicSharedMemorySize, S512);
    cudaFuncSetAttribute(mma_gemm<128,1,1,1>, cudaFuncAttributeMaxDynamicSharedMemorySize, S128);
    cudaFuncSetAttribute(mma_gemm<128,0,1,1>, cudaFuncAttributeMaxDynamicSharedMemorySize, S128);

    // 0. weight transpose -> bf16 [N,K]
    dim3 tb(32, 8);
    transpose_kernel<<<dim3(VV/32, DENC/32), tb>>>(W_enc, wt + O_ENC, DENC, VV);
    transpose_kernel<<<dim3(PP/32, DENC/32), tb>>>(W_p1,  wt + O_P1,  DENC, PP);
    transpose_kernel<<<dim3(PP/32, PP/32),   tb>>>(W_p2,  wt + O_P2,  PP,   PP);
    transpose_kernel<<<dim3(VV/32, PP/32),   tb>>>(W_po,  wt + O_PO,  PP,   VV);
    transpose_kernel<<<dim3(JJ/32, VV/32),   tb>>>(W_j1,  wt + O_J1,  VV,   JJ);
    transpose_kernel<<<dim3(VV/32, JJ/32),   tb>>>(W_j2,  wt + O_J2,  JJ,   VV);

    // 0b. fp32 -> bf16 conversions (encoder_out, emb)
    {
        int n4 = MM * DENC / 4;
        f2bf_kernel<<<(n4 + 255) / 256, 256>>>(encoder_out, encbf, n4);
        int e4 = VV * EE / 4;
        f2bf_kernel<<<(e4 + 255) / 256, 256>>>(emb, embbf, e4);
    }

    // 1. viterbi context
    ctx_kernel<<<BB, 256>>>(targets);

    const int MT = MM / BM;  // 250

    // 2. enc = encoder_out @ W_enc + b_enc  (fp32 out)
    mma_gemm<512,0,0,0><<<dim3(MT, 2), 256, S512>>>(
        encbf, wt + O_ENC, b_enc, enc, nullptr, nullptr, DENC, VV);

    // 3. a1 = tanh(gather @ W_p1 + b_p1)  (bf16 out)
    mma_gemm<512,1,1,1><<<dim3(MT, 1), 256, S512>>>(
        nullptr, wt + O_P1, b_p1, hb1, nullptr, nullptr, DENC, PP);
    mma_gemm<128,1,1,1><<<dim3(MT, 1), 256, S128>>>(
        nullptr, wt + O_P1 + (size_t)512 * DENC, b_p1 + 512, hb1 + 512, nullptr, nullptr, DENC, PP);

    // 4. a2 = tanh(a1 @ W_p2 + b_p2)  (bf16 out)
    mma_gemm<512,0,1,1><<<dim3(MT, 1), 256, S512>>>(
        hb1, wt + O_P2, b_p2, hb2, nullptr, nullptr, PP, PP);
    mma_gemm<128,0,1,1><<<dim3(MT, 1), 256, S128>>>(
        hb1, wt + O_P2 + (size_t)512 * PP, b_p2 + 512, hb2 + 512, nullptr, nullptr, PP, PP);

    // 5. pred = a2 @ W_po + b_po (fp32) ; hsum = bf16(pred + enc)
    mma_gemm<512,0,0,2><<<dim3(MT, 2), 256, S512>>>(
        hb2, wt + O_PO, b_po, pred, enc, hsum, PP, VV);

    // 6. h = tanh(hsum @ W_j1 + b_j1)  (bf16 out)
    mma_gemm<512,0,1,1><<<dim3(MT, 1), 256, S512>>>(
        hsum, wt + O_J1, b_j1, hb1, nullptr, nullptr, VV, JJ);
    mma_gemm<128,0,1,1><<<dim3(MT, 1), 256, S128>>>(
        hsum, wt + O_J1 + (size_t)512 * VV, b_j1 + 512, hb1 + 512, nullptr, nullptr, VV, JJ);

    // 7. logits = h @ W_j2 + b_j2  (fp32 out)
    mma_gemm<512,0,0,0><<<dim3(MT, 2), 256, S512>>>(
        hb1, wt + O_J2, b_j2, logits, nullptr, nullptr, JJ, VV);

    // 8. log-softmaxes
    logsoftmax_kernel<<<MM, 256>>>(logits, out_log);
    logsoftmax_kernel<<<MM, 256>>>(pred,   out_pred);
    logsoftmax_kernel<<<MM, 256>>>(enc,    out_enc);

    // 9. enc_lens
    lens_kernel<<<1, 32>>>(features_len, out_lens);
}